// round 14
// baseline (speedup 1.0000x reference)
#include <cuda_runtime.h>

#define BB 2
#define SS 2048
#define DM 4096
#define NH 32
#define HD 128
#define QL 12
#define KL 4
#define NT (BB*SS)   // 4096 tokens
#define PSL 512      // proj stage-1: d-values per slice
#define NSL (DM/PSL) // 8 slices

typedef unsigned long long u64;

// ---------------- f32x2 packed-math helpers (sm_103a) ----------------------
__device__ __forceinline__ u64 f2pack(float lo, float hi) {
    u64 r; asm("mov.b64 %0, {%1, %2};" : "=l"(r) : "f"(lo), "f"(hi)); return r;
}
__device__ __forceinline__ void f2unpack(u64 v, float& lo, float& hi) {
    asm("mov.b64 {%0, %1}, %2;" : "=f"(lo), "=f"(hi) : "l"(v));
}
__device__ __forceinline__ u64 f2fma(u64 a, u64 b, u64 c) {
    u64 d; asm("fma.rn.f32x2 %0, %1, %2, %3;" : "=l"(d) : "l"(a), "l"(b), "l"(c)); return d;
}
__device__ __forceinline__ u64 f2mul(u64 a, u64 b) {
    u64 d; asm("mul.rn.f32x2 %0, %1, %2;" : "=l"(d) : "l"(a), "l"(b)); return d;
}
__device__ __forceinline__ u64 f2add(u64 a, u64 b) {
    u64 d; asm("add.rn.f32x2 %0, %1, %2;" : "=l"(d) : "l"(a), "l"(b)); return d;
}
__device__ __forceinline__ float ex2f(float x) {
    float y; asm("ex2.approx.f32 %0, %1;" : "=f"(y) : "f"(x)); return y;
}

// ---------------- scratch (device globals; no allocations) ----------------
__device__ __align__(16) float g_part[NSL*NT*16];   // 2 MB  proj partials
__device__ __align__(16) float g_Ckv[NT*KL];        // 64 KB
__device__ __align__(16) float g_q  [NT*NH*KL];     // 2 MB  (pre-scaled by 0.5*log2e)
__device__ __align__(16) float g_A  [NT*NH*KL];     // 2 MB
__device__ __align__(16) float g_M  [NH*KL*DM];     // 2 MB
__device__ __align__(16) float g_Mb [NH*DM];        // 512 KB

#define QSCALE 0.7213475204444817f   /* 0.5 * log2(e) */

// ============ Kernel 1a: proj stage 1 (round-13 known-good) =================
__global__ __launch_bounds__(128) void proj1_kernel(
    const float* __restrict__ x, const float* __restrict__ Wq,
    const float* __restrict__ Wkv)
{
    __shared__ __align__(16) float wsl[PSL][16];
    const int tid = threadIdx.x;
    const int tok = blockIdx.x * 128 + tid;
    const int d0  = blockIdx.y * PSL;

    #pragma unroll
    for (int i = tid; i < PSL*16; i += 128) {
        int d = i >> 4, c = i & 15;
        wsl[d][c] = (c < QL) ? Wq[(size_t)(d0 + d)*QL + c]
                             : Wkv[(size_t)(d0 + d)*KL + (c - QL)];
    }
    __syncthreads();

    u64 acc[8];
    #pragma unroll
    for (int p = 0; p < 8; ++p) acc[p] = 0ull;

    const float* xp = &x[(size_t)tok*DM + d0];
    #pragma unroll 4
    for (int i = 0; i < PSL/4; ++i) {
        float4 xv = *(const float4*)&xp[i*4];
        u64 x0 = f2pack(xv.x, xv.x);
        u64 x1 = f2pack(xv.y, xv.y);
        u64 x2 = f2pack(xv.z, xv.z);
        u64 x3 = f2pack(xv.w, xv.w);
        const u64* w0 = (const u64*)&wsl[i*4 + 0][0];
        const u64* w1 = (const u64*)&wsl[i*4 + 1][0];
        const u64* w2 = (const u64*)&wsl[i*4 + 2][0];
        const u64* w3 = (const u64*)&wsl[i*4 + 3][0];
        #pragma unroll
        for (int p = 0; p < 8; ++p) {
            acc[p] = f2fma(x0, w0[p], acc[p]);
            acc[p] = f2fma(x1, w1[p], acc[p]);
            acc[p] = f2fma(x2, w2[p], acc[p]);
            acc[p] = f2fma(x3, w3[p], acc[p]);
        }
    }

    float* dst = &g_part[((size_t)blockIdx.y*NT + tok)*16];
    #pragma unroll
    for (int p = 0; p < 8; p += 2) {
        float a, b, c2, d2;
        f2unpack(acc[p],   a, b);
        f2unpack(acc[p+1], c2, d2);
        float4 v; v.x = a; v.y = b; v.z = c2; v.w = d2;
        *(float4*)&dst[p*2] = v;
    }
}

// ============ Kernel 1b: proj stage 2 (round-13 known-good) =================
__global__ __launch_bounds__(256) void proj2_kernel(
    const float* __restrict__ bq,  const float* __restrict__ Wqk,
    const float* __restrict__ bqk, const float* __restrict__ bkv)
{
    __shared__ float cq[16][16];
    const int tid = threadIdx.x;
    const int tok = blockIdx.x * 16 + (tid >> 4);
    const int c   = tid & 15;

    float s = (c < QL) ? bq[c] : bkv[c - QL];
    #pragma unroll
    for (int sl = 0; sl < NSL; ++sl)
        s += g_part[((size_t)sl*NT + tok)*16 + c];
    cq[tid >> 4][c] = s;
    if (c >= QL) g_Ckv[(size_t)tok*KL + (c - QL)] = s;
    __syncthreads();

    float cql[QL];
    #pragma unroll
    for (int i = 0; i < QL; ++i) cql[i] = cq[tid >> 4][i];
    const int o0 = c * 8;
    #pragma unroll
    for (int oo = 0; oo < 8; ++oo) {
        int o = o0 + oo;
        float q = bqk[o];
        #pragma unroll
        for (int i = 0; i < QL; ++i) q = fmaf(cql[i], Wqk[i*(NH*KL) + o], q);
        g_q[(size_t)tok*(NH*KL) + o] = QSCALE * q;
    }
}

// ============ Kernel 2: fold Wv_u into Wo (round-12 known-good) =============
__global__ __launch_bounds__(128) void precM_kernel(
    const float* __restrict__ Wvu, const float* __restrict__ Wo,
    const float* __restrict__ bvu)
{
    __shared__ float vu[KL][HD];
    __shared__ float bvs[HD];
    const int h = blockIdx.y;
    const int j = (blockIdx.x * 128 + threadIdx.x) * 4;
    #pragma unroll
    for (int s = 0; s < 4; ++s) {
        int i = threadIdx.x + s*128;
        vu[i >> 7][i & 127] = Wvu[(size_t)(i >> 7)*(NH*HD) + h*HD + (i & 127)];
    }
    bvs[threadIdx.x] = bvu[h*HD + threadIdx.x];
    __syncthreads();

    float4 a0 = {0,0,0,0}, a1 = a0, a2 = a0, a3 = a0, ab = a0;
    #pragma unroll 8
    for (int d = 0; d < HD; ++d) {
        float4 w = *(const float4*)&Wo[(size_t)(h*HD + d)*DM + j];
        float v0 = vu[0][d], v1 = vu[1][d], v2 = vu[2][d], v3 = vu[3][d], vb = bvs[d];
        a0.x=fmaf(v0,w.x,a0.x); a0.y=fmaf(v0,w.y,a0.y); a0.z=fmaf(v0,w.z,a0.z); a0.w=fmaf(v0,w.w,a0.w);
        a1.x=fmaf(v1,w.x,a1.x); a1.y=fmaf(v1,w.y,a1.y); a1.z=fmaf(v1,w.z,a1.z); a1.w=fmaf(v1,w.w,a1.w);
        a2.x=fmaf(v2,w.x,a2.x); a2.y=fmaf(v2,w.y,a2.y); a2.z=fmaf(v2,w.z,a2.z); a2.w=fmaf(v2,w.w,a2.w);
        a3.x=fmaf(v3,w.x,a3.x); a3.y=fmaf(v3,w.y,a3.y); a3.z=fmaf(v3,w.z,a3.z); a3.w=fmaf(v3,w.w,a3.w);
        ab.x=fmaf(vb,w.x,ab.x); ab.y=fmaf(vb,w.y,ab.y); ab.z=fmaf(vb,w.z,ab.z); ab.w=fmaf(vb,w.w,ab.w);
    }
    *(float4*)&g_M[(size_t)(h*KL + 0)*DM + j] = a0;
    *(float4*)&g_M[(size_t)(h*KL + 1)*DM + j] = a1;
    *(float4*)&g_M[(size_t)(h*KL + 2)*DM + j] = a2;
    *(float4*)&g_M[(size_t)(h*KL + 3)*DM + j] = a3;
    *(float4*)&g_Mb[(size_t)h*DM + j] = ab;
}

// ============ Kernel 3: latent attention — 2 queries/thread, 4 chains =======
// grid (8 q-tiles of 256, 32 h, 2 b) = 512 CTAs x 128 thr: ONE wave.
// Key loads (broadcast LDS.128) amortized over 2 queries; 4 independent
// score chains (A0/A1 for query A, B0/B1 for query B).
__global__ __launch_bounds__(128) void attn_kernel()
{
    __shared__ __align__(16) float ckx[SS];
    __shared__ __align__(16) float cky[SS];
    __shared__ __align__(16) float ckz[SS];
    __shared__ __align__(16) float ckw[SS];
    const int b = blockIdx.z, h = blockIdx.y;
    const float4* ckv = (const float4*)(g_Ckv + (size_t)b*SS*KL);
    for (int i = threadIdx.x; i < SS; i += 128) {
        float4 v = ckv[i];
        ckx[i] = v.x; cky[i] = v.y; ckz[i] = v.z; ckw[i] = v.w;
    }
    __syncthreads();

    const int tokA = b*SS + blockIdx.x*256 + threadIdx.x;
    const int tokB = tokA + 128;
    const float4 qA = *(const float4*)(g_q + (size_t)tokA*(NH*KL) + h*KL);
    const float4 qB = *(const float4*)(g_q + (size_t)tokB*(NH*KL) + h*KL);
    const u64 qxA = f2pack(qA.x, qA.x), qyA = f2pack(qA.y, qA.y);
    const u64 qzA = f2pack(qA.z, qA.z), qwA = f2pack(qA.w, qA.w);
    const u64 qxB = f2pack(qB.x, qB.x), qyB = f2pack(qB.y, qB.y);
    const u64 qzB = f2pack(qB.z, qB.z), qwB = f2pack(qB.w, qB.w);

    const ulonglong2* cxp = (const ulonglong2*)ckx;
    const ulonglong2* cyp = (const ulonglong2*)cky;
    const ulonglong2* czp = (const ulonglong2*)ckz;
    const ulonglong2* cwp = (const ulonglong2*)ckw;

    u64 lA0=0ull, axA0=0ull, ayA0=0ull, azA0=0ull, awA0=0ull;
    u64 lA1=0ull, axA1=0ull, ayA1=0ull, azA1=0ull, awA1=0ull;
    u64 lB0=0ull, axB0=0ull, ayB0=0ull, azB0=0ull, awB0=0ull;
    u64 lB1=0ull, axB1=0ull, ayB1=0ull, azB1=0ull, awB1=0ull;

    #pragma unroll 2
    for (int k = 0; k < SS/4; ++k) {
        ulonglong2 cx2 = cxp[k], cy2 = cyp[k], cz2 = czp[k], cw2 = cwp[k];
        // 4 independent score chains
        u64 sA0 = f2mul(qxA, cx2.x);
        u64 sA1 = f2mul(qxA, cx2.y);
        u64 sB0 = f2mul(qxB, cx2.x);
        u64 sB1 = f2mul(qxB, cx2.y);
        sA0 = f2fma(qyA, cy2.x, sA0);  sA1 = f2fma(qyA, cy2.y, sA1);
        sB0 = f2fma(qyB, cy2.x, sB0);  sB1 = f2fma(qyB, cy2.y, sB1);
        sA0 = f2fma(qzA, cz2.x, sA0);  sA1 = f2fma(qzA, cz2.y, sA1);
        sB0 = f2fma(qzB, cz2.x, sB0);  sB1 = f2fma(qzB, cz2.y, sB1);
        sA0 = f2fma(qwA, cw2.x, sA0);  sA1 = f2fma(qwA, cw2.y, sA1);
        sB0 = f2fma(qwB, cw2.x, sB0);  sB1 = f2fma(qwB, cw2.y, sB1);
        float a0,a1,a2,a3, b0,b1,b2,b3;
        f2unpack(sA0, a0, a1); f2unpack(sA1, a2, a3);
        f2unpack(sB0, b0, b1); f2unpack(sB1, b2, b3);
        u64 eA0 = f2pack(ex2f(a0), ex2f(a1));
        u64 eA1 = f2pack(ex2f(a2), ex2f(a3));
        u64 eB0 = f2pack(ex2f(b0), ex2f(b1));
        u64 eB1 = f2pack(ex2f(b2), ex2f(b3));
        lA0  = f2add(lA0, eA0);            lA1  = f2add(lA1, eA1);
        lB0  = f2add(lB0, eB0);            lB1  = f2add(lB1, eB1);
        axA0 = f2fma(eA0, cx2.x, axA0);    axA1 = f2fma(eA1, cx2.y, axA1);
        axB0 = f2fma(eB0, cx2.x, axB0);    axB1 = f2fma(eB1, cx2.y, axB1);
        ayA0 = f2fma(eA0, cy2.x, ayA0);    ayA1 = f2fma(eA1, cy2.y, ayA1);
        ayB0 = f2fma(eB0, cy2.x, ayB0);    ayB1 = f2fma(eB1, cy2.y, ayB1);
        azA0 = f2fma(eA0, cz2.x, azA0);    azA1 = f2fma(eA1, cz2.y, azA1);
        azB0 = f2fma(eB0, cz2.x, azB0);    azB1 = f2fma(eB1, cz2.y, azB1);
        awA0 = f2fma(eA0, cw2.x, awA0);    awA1 = f2fma(eA1, cw2.y, awA1);
        awB0 = f2fma(eB0, cw2.x, awB0);    awB1 = f2fma(eB1, cw2.y, awB1);
    }

    // epilogue for query A
    {
        u64 l2  = f2add(lA0, lA1);
        u64 ax2 = f2add(axA0, axA1), ay2 = f2add(ayA0, ayA1);
        u64 az2 = f2add(azA0, azA1), aw2 = f2add(awA0, awA1);
        float l0,l1,x0,x1,y0,y1,z0,z1,w0,w1;
        f2unpack(l2, l0, l1);
        f2unpack(ax2, x0, x1); f2unpack(ay2, y0, y1);
        f2unpack(az2, z0, z1); f2unpack(aw2, w0, w1);
        float inv = 1.f / (l0 + l1);
        float4 r;
        r.x = (x0 + x1) * inv; r.y = (y0 + y1) * inv;
        r.z = (z0 + z1) * inv; r.w = (w0 + w1) * inv;
        *(float4*)(g_A + (size_t)tokA*(NH*KL) + h*KL) = r;
    }
    // epilogue for query B
    {
        u64 l2  = f2add(lB0, lB1);
        u64 ax2 = f2add(axB0, axB1), ay2 = f2add(ayB0, ayB1);
        u64 az2 = f2add(azB0, azB1), aw2 = f2add(awB0, awB1);
        float l0,l1,x0,x1,y0,y1,z0,z1,w0,w1;
        f2unpack(l2, l0, l1);
        f2unpack(ax2, x0, x1); f2unpack(ay2, y0, y1);
        f2unpack(az2, z0, z1); f2unpack(aw2, w0, w1);
        float inv = 1.f / (l0 + l1);
        float4 r;
        r.x = (x0 + x1) * inv; r.y = (y0 + y1) * inv;
        r.z = (z0 + z1) * inv; r.w = (w0 + w1) * inv;
        *(float4*)(g_A + (size_t)tokB*(NH*KL) + h*KL) = r;
    }
}

// ============ Kernel 4: out = A @ M + (bo + sum_h Mb) (round-12 known-good) =
__global__ __launch_bounds__(256, 2) void final_kernel(
    float* __restrict__ out, const float* __restrict__ bo)
{
    __shared__ __align__(16) float Ast[16][258];   // [k][row]
    __shared__ __align__(16) float Bs[16][68];     // [k][j]
    const int tok0 = blockIdx.y * 256, j0 = blockIdx.x * 64;
    const int tid = threadIdx.x;
    const int tx = tid & 15, ty = tid >> 4;

    const int ar  = tid >> 2;          // base row 0..63 (+64*s)
    const int akq = (tid & 3) * 4;     // k quad 0,4,8,12
    const int bk  = tid >> 4;          // 0..15
    const int bjq = (tid & 15) * 4;

    u64 acc[8][4];
    #pragma unroll
    for (int i = 0; i < 8; ++i)
        #pragma unroll
        for (int j = 0; j < 4; ++j) acc[i][j] = 0ull;

    float4 aA[4], aB;
    #pragma unroll
    for (int s = 0; s < 4; ++s)
        aA[s] = *(const float4*)&g_A[(size_t)(tok0 + ar + 64*s)*(NH*KL) + akq];
    aB = *(const float4*)&g_M[(size_t)bk*DM + j0 + bjq];

    for (int k0 = 0; k0 < NH*KL; k0 += 16) {
        #pragma unroll
        for (int s = 0; s < 4; ++s) {
            int r = ar + 64*s;
            Ast[akq+0][r] = aA[s].x; Ast[akq+1][r] = aA[s].y;
            Ast[akq+2][r] = aA[s].z; Ast[akq+3][r] = aA[s].w;
        }
        *(float4*)&Bs[bk][bjq] = aB;
        __syncthreads();
        if (k0 + 16 < NH*KL) {
            #pragma unroll
            for (int s = 0; s < 4; ++s)
                aA[s] = *(const float4*)&g_A[(size_t)(tok0 + ar + 64*s)*(NH*KL) + k0 + 16 + akq];
            aB = *(const float4*)&g_M[(size_t)(k0 + 16 + bk)*DM + j0 + bjq];
        }
        #pragma unroll
        for (int k = 0; k < 16; ++k) {
            float4 bv = *(const float4*)&Bs[k][tx*4];
            u64 b0 = f2pack(bv.x, bv.x);
            u64 b1 = f2pack(bv.y, bv.y);
            u64 b2 = f2pack(bv.z, bv.z);
            u64 b3 = f2pack(bv.w, bv.w);
            #pragma unroll
            for (int i = 0; i < 8; ++i) {
                u64 a = *(const u64*)&Ast[k][ty*2 + 32*i];
                acc[i][0] = f2fma(a, b0, acc[i][0]);
                acc[i][1] = f2fma(a, b1, acc[i][1]);
                acc[i][2] = f2fma(a, b2, acc[i][2]);
                acc[i][3] = f2fma(a, b3, acc[i][3]);
            }
        }
        __syncthreads();
    }

    float4 bj = *(const float4*)&bo[j0 + tx*4];
    #pragma unroll
    for (int h = 0; h < NH; ++h) {
        float4 m = *(const float4*)&g_Mb[(size_t)h*DM + j0 + tx*4];
        bj.x += m.x; bj.y += m.y; bj.z += m.z; bj.w += m.w;
    }

    #pragma unroll
    for (int i = 0; i < 8; ++i) {
        float lo0, hi0, lo1, hi1, lo2, hi2, lo3, hi3;
        f2unpack(acc[i][0], lo0, hi0);
        f2unpack(acc[i][1], lo1, hi1);
        f2unpack(acc[i][2], lo2, hi2);
        f2unpack(acc[i][3], lo3, hi3);
        float4 ra, rb;
        ra.x = lo0 + bj.x; ra.y = lo1 + bj.y; ra.z = lo2 + bj.z; ra.w = lo3 + bj.w;
        rb.x = hi0 + bj.x; rb.y = hi1 + bj.y; rb.z = hi2 + bj.z; rb.w = hi3 + bj.w;
        size_t row = (size_t)(tok0 + ty*2 + 32*i);
        *(float4*)&out[row*DM + j0 + tx*4]       = ra;
        *(float4*)&out[(row + 1)*DM + j0 + tx*4] = rb;
    }
}

// ============================================================================
extern "C" void kernel_launch(void* const* d_in, const int* in_sizes, int n_in,
                              void* d_out, int out_size)
{
    const float* x    = (const float*)d_in[0];
    const float* Wq_d = (const float*)d_in[1];
    const float* bq_d = (const float*)d_in[2];
    const float* W_qk = (const float*)d_in[3];
    const float* b_qk = (const float*)d_in[4];
    const float* Wkv_d= (const float*)d_in[5];
    const float* bkv_d= (const float*)d_in[6];
    const float* Wv_u = (const float*)d_in[7];
    const float* bv_u = (const float*)d_in[8];
    const float* Wo   = (const float*)d_in[9];
    const float* bo   = (const float*)d_in[10];
    float* out = (float*)d_out;

    proj1_kernel<<<dim3(NT/128, NSL), 128>>>(x, Wq_d, Wkv_d);
    proj2_kernel<<<NT/16, 256>>>(bq_d, W_qk, b_qk, bkv_d);
    precM_kernel<<<dim3(DM/512, NH), 128>>>(Wv_u, Wo, bv_u);
    attn_kernel<<<dim3(SS/256, NH, BB), 128>>>();
    final_kernel<<<dim3(DM/64, NT/256), 256>>>(out, bo);
}

// round 15
// speedup vs baseline: 1.0139x; 1.0139x over previous
#include <cuda_runtime.h>

#define BB 2
#define SS 2048
#define DM 4096
#define NH 32
#define HD 128
#define QL 12
#define KL 4
#define NT (BB*SS)   // 4096 tokens
#define PSL 512      // proj stage-1: d-values per slice
#define NSL (DM/PSL) // 8 slices

typedef unsigned long long u64;

// ---------------- f32x2 packed-math helpers (sm_103a) ----------------------
__device__ __forceinline__ u64 f2pack(float lo, float hi) {
    u64 r; asm("mov.b64 %0, {%1, %2};" : "=l"(r) : "f"(lo), "f"(hi)); return r;
}
__device__ __forceinline__ void f2unpack(u64 v, float& lo, float& hi) {
    asm("mov.b64 {%0, %1}, %2;" : "=f"(lo), "=f"(hi) : "l"(v));
}
__device__ __forceinline__ u64 f2fma(u64 a, u64 b, u64 c) {
    u64 d; asm("fma.rn.f32x2 %0, %1, %2, %3;" : "=l"(d) : "l"(a), "l"(b), "l"(c)); return d;
}
__device__ __forceinline__ u64 f2mul(u64 a, u64 b) {
    u64 d; asm("mul.rn.f32x2 %0, %1, %2;" : "=l"(d) : "l"(a), "l"(b)); return d;
}
__device__ __forceinline__ u64 f2add(u64 a, u64 b) {
    u64 d; asm("add.rn.f32x2 %0, %1, %2;" : "=l"(d) : "l"(a), "l"(b)); return d;
}
__device__ __forceinline__ float ex2f(float x) {
    float y; asm("ex2.approx.f32 %0, %1;" : "=f"(y) : "f"(x)); return y;
}

// ---------------- scratch (device globals; no allocations) ----------------
__device__ __align__(16) float g_part[NSL*NT*16];   // 2 MB  proj partials
__device__ __align__(16) float g_Ckv[NT*KL];        // 64 KB
__device__ __align__(16) float g_q  [NT*NH*KL];     // 2 MB  (pre-scaled by 0.5*log2e)
__device__ __align__(16) float g_A  [NT*NH*KL];     // 2 MB
__device__ __align__(16) float g_M  [NH*KL*DM];     // 2 MB
__device__ __align__(16) float g_Mb [NH*DM];        // 512 KB

#define QSCALE 0.7213475204444817f   /* 0.5 * log2(e) */

// ============ Kernel 1a: proj stage 1 (round-13 known-good) =================
__global__ __launch_bounds__(128) void proj1_kernel(
    const float* __restrict__ x, const float* __restrict__ Wq,
    const float* __restrict__ Wkv)
{
    __shared__ __align__(16) float wsl[PSL][16];
    const int tid = threadIdx.x;
    const int tok = blockIdx.x * 128 + tid;
    const int d0  = blockIdx.y * PSL;

    #pragma unroll
    for (int i = tid; i < PSL*16; i += 128) {
        int d = i >> 4, c = i & 15;
        wsl[d][c] = (c < QL) ? Wq[(size_t)(d0 + d)*QL + c]
                             : Wkv[(size_t)(d0 + d)*KL + (c - QL)];
    }
    __syncthreads();

    u64 acc[8];
    #pragma unroll
    for (int p = 0; p < 8; ++p) acc[p] = 0ull;

    const float* xp = &x[(size_t)tok*DM + d0];
    #pragma unroll 4
    for (int i = 0; i < PSL/4; ++i) {
        float4 xv = *(const float4*)&xp[i*4];
        u64 x0 = f2pack(xv.x, xv.x);
        u64 x1 = f2pack(xv.y, xv.y);
        u64 x2 = f2pack(xv.z, xv.z);
        u64 x3 = f2pack(xv.w, xv.w);
        const u64* w0 = (const u64*)&wsl[i*4 + 0][0];
        const u64* w1 = (const u64*)&wsl[i*4 + 1][0];
        const u64* w2 = (const u64*)&wsl[i*4 + 2][0];
        const u64* w3 = (const u64*)&wsl[i*4 + 3][0];
        #pragma unroll
        for (int p = 0; p < 8; ++p) {
            acc[p] = f2fma(x0, w0[p], acc[p]);
            acc[p] = f2fma(x1, w1[p], acc[p]);
            acc[p] = f2fma(x2, w2[p], acc[p]);
            acc[p] = f2fma(x3, w3[p], acc[p]);
        }
    }

    float* dst = &g_part[((size_t)blockIdx.y*NT + tok)*16];
    #pragma unroll
    for (int p = 0; p < 8; p += 2) {
        float a, b, c2, d2;
        f2unpack(acc[p],   a, b);
        f2unpack(acc[p+1], c2, d2);
        float4 v; v.x = a; v.y = b; v.z = c2; v.w = d2;
        *(float4*)&dst[p*2] = v;
    }
}

// ============ Kernel 1b: proj stage 2 (round-13 known-good) =================
__global__ __launch_bounds__(256) void proj2_kernel(
    const float* __restrict__ bq,  const float* __restrict__ Wqk,
    const float* __restrict__ bqk, const float* __restrict__ bkv)
{
    __shared__ float cq[16][16];
    const int tid = threadIdx.x;
    const int tok = blockIdx.x * 16 + (tid >> 4);
    const int c   = tid & 15;

    float s = (c < QL) ? bq[c] : bkv[c - QL];
    #pragma unroll
    for (int sl = 0; sl < NSL; ++sl)
        s += g_part[((size_t)sl*NT + tok)*16 + c];
    cq[tid >> 4][c] = s;
    if (c >= QL) g_Ckv[(size_t)tok*KL + (c - QL)] = s;
    __syncthreads();

    float cql[QL];
    #pragma unroll
    for (int i = 0; i < QL; ++i) cql[i] = cq[tid >> 4][i];
    const int o0 = c * 8;
    #pragma unroll
    for (int oo = 0; oo < 8; ++oo) {
        int o = o0 + oo;
        float q = bqk[o];
        #pragma unroll
        for (int i = 0; i < QL; ++i) q = fmaf(cql[i], Wqk[i*(NH*KL) + o], q);
        g_q[(size_t)tok*(NH*KL) + o] = QSCALE * q;
    }
}

// ============ Kernel 2: fold Wv_u into Wo (round-12 known-good) =============
__global__ __launch_bounds__(128) void precM_kernel(
    const float* __restrict__ Wvu, const float* __restrict__ Wo,
    const float* __restrict__ bvu)
{
    __shared__ float vu[KL][HD];
    __shared__ float bvs[HD];
    const int h = blockIdx.y;
    const int j = (blockIdx.x * 128 + threadIdx.x) * 4;
    #pragma unroll
    for (int s = 0; s < 4; ++s) {
        int i = threadIdx.x + s*128;
        vu[i >> 7][i & 127] = Wvu[(size_t)(i >> 7)*(NH*HD) + h*HD + (i & 127)];
    }
    bvs[threadIdx.x] = bvu[h*HD + threadIdx.x];
    __syncthreads();

    float4 a0 = {0,0,0,0}, a1 = a0, a2 = a0, a3 = a0, ab = a0;
    #pragma unroll 8
    for (int d = 0; d < HD; ++d) {
        float4 w = *(const float4*)&Wo[(size_t)(h*HD + d)*DM + j];
        float v0 = vu[0][d], v1 = vu[1][d], v2 = vu[2][d], v3 = vu[3][d], vb = bvs[d];
        a0.x=fmaf(v0,w.x,a0.x); a0.y=fmaf(v0,w.y,a0.y); a0.z=fmaf(v0,w.z,a0.z); a0.w=fmaf(v0,w.w,a0.w);
        a1.x=fmaf(v1,w.x,a1.x); a1.y=fmaf(v1,w.y,a1.y); a1.z=fmaf(v1,w.z,a1.z); a1.w=fmaf(v1,w.w,a1.w);
        a2.x=fmaf(v2,w.x,a2.x); a2.y=fmaf(v2,w.y,a2.y); a2.z=fmaf(v2,w.z,a2.z); a2.w=fmaf(v2,w.w,a2.w);
        a3.x=fmaf(v3,w.x,a3.x); a3.y=fmaf(v3,w.y,a3.y); a3.z=fmaf(v3,w.z,a3.z); a3.w=fmaf(v3,w.w,a3.w);
        ab.x=fmaf(vb,w.x,ab.x); ab.y=fmaf(vb,w.y,ab.y); ab.z=fmaf(vb,w.z,ab.z); ab.w=fmaf(vb,w.w,ab.w);
    }
    *(float4*)&g_M[(size_t)(h*KL + 0)*DM + j] = a0;
    *(float4*)&g_M[(size_t)(h*KL + 1)*DM + j] = a1;
    *(float4*)&g_M[(size_t)(h*KL + 2)*DM + j] = a2;
    *(float4*)&g_M[(size_t)(h*KL + 3)*DM + j] = a3;
    *(float4*)&g_Mb[(size_t)h*DM + j] = ab;
}

// ============ Kernel 3: latent attention — r13 body, one-wave grid ==========
// grid (8 q-tiles of 256, 32 h, 2 b) = 512 CTAs x 256 thr; thread = 1 query.
// 6 CTAs/SM resident (33KB smem) -> all 512 CTAs in ONE wave, zero tail.
__global__ __launch_bounds__(256) void attn_kernel()
{
    __shared__ __align__(16) float ckx[SS];
    __shared__ __align__(16) float cky[SS];
    __shared__ __align__(16) float ckz[SS];
    __shared__ __align__(16) float ckw[SS];
    const int b = blockIdx.z, h = blockIdx.y;
    const float4* ckv = (const float4*)(g_Ckv + (size_t)b*SS*KL);
    for (int i = threadIdx.x; i < SS; i += 256) {
        float4 v = ckv[i];
        ckx[i] = v.x; cky[i] = v.y; ckz[i] = v.z; ckw[i] = v.w;
    }
    __syncthreads();

    const int tok = b*SS + blockIdx.x*256 + threadIdx.x;
    const float4 qv = *(const float4*)(g_q + (size_t)tok*(NH*KL) + h*KL);
    const u64 qx2 = f2pack(qv.x, qv.x);
    const u64 qy2 = f2pack(qv.y, qv.y);
    const u64 qz2 = f2pack(qv.z, qv.z);
    const u64 qw2 = f2pack(qv.w, qv.w);

    const ulonglong2* cxp = (const ulonglong2*)ckx;
    const ulonglong2* cyp = (const ulonglong2*)cky;
    const ulonglong2* czp = (const ulonglong2*)ckz;
    const ulonglong2* cwp = (const ulonglong2*)ckw;

    u64 lA=0ull, axA=0ull, ayA=0ull, azA=0ull, awA=0ull;
    u64 lB=0ull, axB=0ull, ayB=0ull, azB=0ull, awB=0ull;
    #pragma unroll 4
    for (int k = 0; k < SS/4; ++k) {
        ulonglong2 cx2 = cxp[k], cy2 = cyp[k], cz2 = czp[k], cw2 = cwp[k];
        u64 sa = f2mul(qx2, cx2.x);
        u64 sb = f2mul(qx2, cx2.y);
        sa = f2fma(qy2, cy2.x, sa);  sb = f2fma(qy2, cy2.y, sb);
        sa = f2fma(qz2, cz2.x, sa);  sb = f2fma(qz2, cz2.y, sb);
        sa = f2fma(qw2, cw2.x, sa);  sb = f2fma(qw2, cw2.y, sb);
        float s0,s1,s2,s3; f2unpack(sa, s0, s1); f2unpack(sb, s2, s3);
        u64 ea = f2pack(ex2f(s0), ex2f(s1));
        u64 eb = f2pack(ex2f(s2), ex2f(s3));
        lA  = f2add(lA, ea);             lB  = f2add(lB, eb);
        axA = f2fma(ea, cx2.x, axA);     axB = f2fma(eb, cx2.y, axB);
        ayA = f2fma(ea, cy2.x, ayA);     ayB = f2fma(eb, cy2.y, ayB);
        azA = f2fma(ea, cz2.x, azA);     azB = f2fma(eb, cz2.y, azB);
        awA = f2fma(ea, cw2.x, awA);     awB = f2fma(eb, cw2.y, awB);
    }
    u64 l2  = f2add(lA, lB);
    u64 ax2 = f2add(axA, axB), ay2 = f2add(ayA, ayB);
    u64 az2 = f2add(azA, azB), aw2 = f2add(awA, awB);
    float l0,l1,x0,x1,y0,y1,z0,z1,w0,w1;
    f2unpack(l2, l0, l1);
    f2unpack(ax2, x0, x1); f2unpack(ay2, y0, y1);
    f2unpack(az2, z0, z1); f2unpack(aw2, w0, w1);
    float inv = 1.f / (l0 + l1);
    float4 r;
    r.x = (x0 + x1) * inv; r.y = (y0 + y1) * inv;
    r.z = (z0 + z1) * inv; r.w = (w0 + w1) * inv;
    *(float4*)(g_A + (size_t)tok*(NH*KL) + h*KL) = r;
}

// ============ Kernel 4: out = A @ M + (bo + sum_h Mb) (round-12 known-good) =
__global__ __launch_bounds__(256, 2) void final_kernel(
    float* __restrict__ out, const float* __restrict__ bo)
{
    __shared__ __align__(16) float Ast[16][258];   // [k][row]
    __shared__ __align__(16) float Bs[16][68];     // [k][j]
    const int tok0 = blockIdx.y * 256, j0 = blockIdx.x * 64;
    const int tid = threadIdx.x;
    const int tx = tid & 15, ty = tid >> 4;

    const int ar  = tid >> 2;          // base row 0..63 (+64*s)
    const int akq = (tid & 3) * 4;     // k quad 0,4,8,12
    const int bk  = tid >> 4;          // 0..15
    const int bjq = (tid & 15) * 4;

    u64 acc[8][4];
    #pragma unroll
    for (int i = 0; i < 8; ++i)
        #pragma unroll
        for (int j = 0; j < 4; ++j) acc[i][j] = 0ull;

    float4 aA[4], aB;
    #pragma unroll
    for (int s = 0; s < 4; ++s)
        aA[s] = *(const float4*)&g_A[(size_t)(tok0 + ar + 64*s)*(NH*KL) + akq];
    aB = *(const float4*)&g_M[(size_t)bk*DM + j0 + bjq];

    for (int k0 = 0; k0 < NH*KL; k0 += 16) {
        #pragma unroll
        for (int s = 0; s < 4; ++s) {
            int r = ar + 64*s;
            Ast[akq+0][r] = aA[s].x; Ast[akq+1][r] = aA[s].y;
            Ast[akq+2][r] = aA[s].z; Ast[akq+3][r] = aA[s].w;
        }
        *(float4*)&Bs[bk][bjq] = aB;
        __syncthreads();
        if (k0 + 16 < NH*KL) {
            #pragma unroll
            for (int s = 0; s < 4; ++s)
                aA[s] = *(const float4*)&g_A[(size_t)(tok0 + ar + 64*s)*(NH*KL) + k0 + 16 + akq];
            aB = *(const float4*)&g_M[(size_t)(k0 + 16 + bk)*DM + j0 + bjq];
        }
        #pragma unroll
        for (int k = 0; k < 16; ++k) {
            float4 bv = *(const float4*)&Bs[k][tx*4];
            u64 b0 = f2pack(bv.x, bv.x);
            u64 b1 = f2pack(bv.y, bv.y);
            u64 b2 = f2pack(bv.z, bv.z);
            u64 b3 = f2pack(bv.w, bv.w);
            #pragma unroll
            for (int i = 0; i < 8; ++i) {
                u64 a = *(const u64*)&Ast[k][ty*2 + 32*i];
                acc[i][0] = f2fma(a, b0, acc[i][0]);
                acc[i][1] = f2fma(a, b1, acc[i][1]);
                acc[i][2] = f2fma(a, b2, acc[i][2]);
                acc[i][3] = f2fma(a, b3, acc[i][3]);
            }
        }
        __syncthreads();
    }

    float4 bj = *(const float4*)&bo[j0 + tx*4];
    #pragma unroll
    for (int h = 0; h < NH; ++h) {
        float4 m = *(const float4*)&g_Mb[(size_t)h*DM + j0 + tx*4];
        bj.x += m.x; bj.y += m.y; bj.z += m.z; bj.w += m.w;
    }

    #pragma unroll
    for (int i = 0; i < 8; ++i) {
        float lo0, hi0, lo1, hi1, lo2, hi2, lo3, hi3;
        f2unpack(acc[i][0], lo0, hi0);
        f2unpack(acc[i][1], lo1, hi1);
        f2unpack(acc[i][2], lo2, hi2);
        f2unpack(acc[i][3], lo3, hi3);
        float4 ra, rb;
        ra.x = lo0 + bj.x; ra.y = lo1 + bj.y; ra.z = lo2 + bj.z; ra.w = lo3 + bj.w;
        rb.x = hi0 + bj.x; rb.y = hi1 + bj.y; rb.z = hi2 + bj.z; rb.w = hi3 + bj.w;
        size_t row = (size_t)(tok0 + ty*2 + 32*i);
        *(float4*)&out[row*DM + j0 + tx*4]       = ra;
        *(float4*)&out[(row + 1)*DM + j0 + tx*4] = rb;
    }
}

// ============================================================================
extern "C" void kernel_launch(void* const* d_in, const int* in_sizes, int n_in,
                              void* d_out, int out_size)
{
    const float* x    = (const float*)d_in[0];
    const float* Wq_d = (const float*)d_in[1];
    const float* bq_d = (const float*)d_in[2];
    const float* W_qk = (const float*)d_in[3];
    const float* b_qk = (const float*)d_in[4];
    const float* Wkv_d= (const float*)d_in[5];
    const float* bkv_d= (const float*)d_in[6];
    const float* Wv_u = (const float*)d_in[7];
    const float* bv_u = (const float*)d_in[8];
    const float* Wo   = (const float*)d_in[9];
    const float* bo   = (const float*)d_in[10];
    float* out = (float*)d_out;

    proj1_kernel<<<dim3(NT/128, NSL), 128>>>(x, Wq_d, Wkv_d);
    proj2_kernel<<<NT/16, 256>>>(bq_d, W_qk, b_qk, bkv_d);
    precM_kernel<<<dim3(DM/512, NH), 128>>>(Wv_u, Wo, bv_u);
    attn_kernel<<<dim3(SS/256, NH, BB), 256>>>();
    final_kernel<<<dim3(DM/64, NT/256), 256>>>(out, bo);
}

// round 16
// speedup vs baseline: 1.1319x; 1.1165x over previous
#include <cuda_runtime.h>

#define BB 2
#define SS 2048
#define DM 4096
#define NH 32
#define HD 128
#define QL 12
#define KL 4
#define NT (BB*SS)   // 4096 tokens
#define PSL 512      // proj stage-1: d-values per slice
#define NSL (DM/PSL) // 8 slices

typedef unsigned long long u64;

// ---------------- f32x2 packed-math helpers (sm_103a) ----------------------
__device__ __forceinline__ u64 f2pack(float lo, float hi) {
    u64 r; asm("mov.b64 %0, {%1, %2};" : "=l"(r) : "f"(lo), "f"(hi)); return r;
}
__device__ __forceinline__ void f2unpack(u64 v, float& lo, float& hi) {
    asm("mov.b64 {%0, %1}, %2;" : "=f"(lo), "=f"(hi) : "l"(v));
}
__device__ __forceinline__ u64 f2fma(u64 a, u64 b, u64 c) {
    u64 d; asm("fma.rn.f32x2 %0, %1, %2, %3;" : "=l"(d) : "l"(a), "l"(b), "l"(c)); return d;
}
__device__ __forceinline__ u64 f2mul(u64 a, u64 b) {
    u64 d; asm("mul.rn.f32x2 %0, %1, %2;" : "=l"(d) : "l"(a), "l"(b)); return d;
}
__device__ __forceinline__ u64 f2add(u64 a, u64 b) {
    u64 d; asm("add.rn.f32x2 %0, %1, %2;" : "=l"(d) : "l"(a), "l"(b)); return d;
}
__device__ __forceinline__ float ex2f(float x) {
    float y; asm("ex2.approx.f32 %0, %1;" : "=f"(y) : "f"(x)); return y;
}

// ---------------- scratch (device globals; no allocations) ----------------
__device__ __align__(16) float g_part[NSL*NT*16];   // 2 MB  proj partials
__device__ __align__(16) float g_Ckv[NT*KL];        // 64 KB
__device__ __align__(16) float g_q  [NT*NH*KL];     // 2 MB  (pre-scaled by 0.5*log2e)
__device__ __align__(16) float g_A  [NT*NH*KL];     // 2 MB
__device__ __align__(16) float g_M  [NH*KL*DM];     // 2 MB
__device__ __align__(16) float g_Mb [NH*DM];        // 512 KB

#define QSCALE 0.7213475204444817f   /* 0.5 * log2(e) */

// ============ Kernel 1: FUSED proj stage-1 + precM (independent work) =======
// blocks [0,256): proj1 role — x @ (Wq||Wkv) partials for one 512-d slice.
// blocks [256,512): precM role — fold Wv_u into Wo for one (head, j-tile).
// Roles have complementary bottlenecks (fma vs DRAM) and co-run in one wave.
__global__ __launch_bounds__(128) void fused_pre_kernel(
    const float* __restrict__ x,   const float* __restrict__ Wq,
    const float* __restrict__ Wkv, const float* __restrict__ Wvu,
    const float* __restrict__ Wo,  const float* __restrict__ bvu)
{
    __shared__ __align__(16) float wsl[PSL][16];   // proj1 weights (32 KB)
    __shared__ float vu[KL][HD];                   // precM Wv_u tile
    __shared__ float bvs[HD];
    const int tid = threadIdx.x;

    if (blockIdx.x < 256) {
        // ---------------- proj1 role (round-13 body) ----------------
        const int bx  = blockIdx.x;
        const int tok = (bx & 31) * 128 + tid;
        const int sl  = bx >> 5;
        const int d0  = sl * PSL;

        #pragma unroll
        for (int i = tid; i < PSL*16; i += 128) {
            int d = i >> 4, c = i & 15;
            wsl[d][c] = (c < QL) ? Wq[(size_t)(d0 + d)*QL + c]
                                 : Wkv[(size_t)(d0 + d)*KL + (c - QL)];
        }
        __syncthreads();

        u64 acc[8];
        #pragma unroll
        for (int p = 0; p < 8; ++p) acc[p] = 0ull;

        const float* xp = &x[(size_t)tok*DM + d0];
        #pragma unroll 4
        for (int i = 0; i < PSL/4; ++i) {
            float4 xv = *(const float4*)&xp[i*4];
            u64 x0 = f2pack(xv.x, xv.x);
            u64 x1 = f2pack(xv.y, xv.y);
            u64 x2 = f2pack(xv.z, xv.z);
            u64 x3 = f2pack(xv.w, xv.w);
            const u64* w0 = (const u64*)&wsl[i*4 + 0][0];
            const u64* w1 = (const u64*)&wsl[i*4 + 1][0];
            const u64* w2 = (const u64*)&wsl[i*4 + 2][0];
            const u64* w3 = (const u64*)&wsl[i*4 + 3][0];
            #pragma unroll
            for (int p = 0; p < 8; ++p) {
                acc[p] = f2fma(x0, w0[p], acc[p]);
                acc[p] = f2fma(x1, w1[p], acc[p]);
                acc[p] = f2fma(x2, w2[p], acc[p]);
                acc[p] = f2fma(x3, w3[p], acc[p]);
            }
        }

        float* dst = &g_part[((size_t)sl*NT + tok)*16];
        #pragma unroll
        for (int p = 0; p < 8; p += 2) {
            float a, b, c2, d2;
            f2unpack(acc[p],   a, b);
            f2unpack(acc[p+1], c2, d2);
            float4 v; v.x = a; v.y = b; v.z = c2; v.w = d2;
            *(float4*)&dst[p*2] = v;
        }
    } else {
        // ---------------- precM role (round-12 body) ----------------
        const int idx = blockIdx.x - 256;
        const int h   = idx >> 3;
        const int j   = ((idx & 7) * 128 + tid) * 4;
        #pragma unroll
        for (int s = 0; s < 4; ++s) {
            int i = tid + s*128;
            vu[i >> 7][i & 127] = Wvu[(size_t)(i >> 7)*(NH*HD) + h*HD + (i & 127)];
        }
        bvs[tid] = bvu[h*HD + tid];
        __syncthreads();

        float4 a0 = {0,0,0,0}, a1 = a0, a2 = a0, a3 = a0, ab = a0;
        #pragma unroll 8
        for (int d = 0; d < HD; ++d) {
            float4 w = *(const float4*)&Wo[(size_t)(h*HD + d)*DM + j];
            float v0 = vu[0][d], v1 = vu[1][d], v2 = vu[2][d], v3 = vu[3][d], vb = bvs[d];
            a0.x=fmaf(v0,w.x,a0.x); a0.y=fmaf(v0,w.y,a0.y); a0.z=fmaf(v0,w.z,a0.z); a0.w=fmaf(v0,w.w,a0.w);
            a1.x=fmaf(v1,w.x,a1.x); a1.y=fmaf(v1,w.y,a1.y); a1.z=fmaf(v1,w.z,a1.z); a1.w=fmaf(v1,w.w,a1.w);
            a2.x=fmaf(v2,w.x,a2.x); a2.y=fmaf(v2,w.y,a2.y); a2.z=fmaf(v2,w.z,a2.z); a2.w=fmaf(v2,w.w,a2.w);
            a3.x=fmaf(v3,w.x,a3.x); a3.y=fmaf(v3,w.y,a3.y); a3.z=fmaf(v3,w.z,a3.z); a3.w=fmaf(v3,w.w,a3.w);
            ab.x=fmaf(vb,w.x,ab.x); ab.y=fmaf(vb,w.y,ab.y); ab.z=fmaf(vb,w.z,ab.z); ab.w=fmaf(vb,w.w,ab.w);
        }
        *(float4*)&g_M[(size_t)(h*KL + 0)*DM + j] = a0;
        *(float4*)&g_M[(size_t)(h*KL + 1)*DM + j] = a1;
        *(float4*)&g_M[(size_t)(h*KL + 2)*DM + j] = a2;
        *(float4*)&g_M[(size_t)(h*KL + 3)*DM + j] = a3;
        *(float4*)&g_Mb[(size_t)h*DM + j] = ab;
    }
}

// ============ Kernel 1b: proj stage 2 (round-13 known-good) =================
__global__ __launch_bounds__(256) void proj2_kernel(
    const float* __restrict__ bq,  const float* __restrict__ Wqk,
    const float* __restrict__ bqk, const float* __restrict__ bkv)
{
    __shared__ float cq[16][16];
    const int tid = threadIdx.x;
    const int tok = blockIdx.x * 16 + (tid >> 4);
    const int c   = tid & 15;

    float s = (c < QL) ? bq[c] : bkv[c - QL];
    #pragma unroll
    for (int sl = 0; sl < NSL; ++sl)
        s += g_part[((size_t)sl*NT + tok)*16 + c];
    cq[tid >> 4][c] = s;
    if (c >= QL) g_Ckv[(size_t)tok*KL + (c - QL)] = s;
    __syncthreads();

    float cql[QL];
    #pragma unroll
    for (int i = 0; i < QL; ++i) cql[i] = cq[tid >> 4][i];
    const int o0 = c * 8;
    #pragma unroll
    for (int oo = 0; oo < 8; ++oo) {
        int o = o0 + oo;
        float q = bqk[o];
        #pragma unroll
        for (int i = 0; i < QL; ++i) q = fmaf(cql[i], Wqk[i*(NH*KL) + o], q);
        g_q[(size_t)tok*(NH*KL) + o] = QSCALE * q;
    }
}

// ============ Kernel 3: latent attention (round-13 known-good: 1024x128) ====
__global__ __launch_bounds__(128) void attn_kernel()
{
    __shared__ __align__(16) float ckx[SS];
    __shared__ __align__(16) float cky[SS];
    __shared__ __align__(16) float ckz[SS];
    __shared__ __align__(16) float ckw[SS];
    const int b = blockIdx.z, h = blockIdx.y;
    const float4* ckv = (const float4*)(g_Ckv + (size_t)b*SS*KL);
    for (int i = threadIdx.x; i < SS; i += 128) {
        float4 v = ckv[i];
        ckx[i] = v.x; cky[i] = v.y; ckz[i] = v.z; ckw[i] = v.w;
    }
    __syncthreads();

    const int tok = b*SS + blockIdx.x*128 + threadIdx.x;
    const float4 qv = *(const float4*)(g_q + (size_t)tok*(NH*KL) + h*KL);
    const u64 qx2 = f2pack(qv.x, qv.x);
    const u64 qy2 = f2pack(qv.y, qv.y);
    const u64 qz2 = f2pack(qv.z, qv.z);
    const u64 qw2 = f2pack(qv.w, qv.w);

    const ulonglong2* cxp = (const ulonglong2*)ckx;
    const ulonglong2* cyp = (const ulonglong2*)cky;
    const ulonglong2* czp = (const ulonglong2*)ckz;
    const ulonglong2* cwp = (const ulonglong2*)ckw;

    u64 lA=0ull, axA=0ull, ayA=0ull, azA=0ull, awA=0ull;
    u64 lB=0ull, axB=0ull, ayB=0ull, azB=0ull, awB=0ull;
    #pragma unroll 4
    for (int k = 0; k < SS/4; ++k) {
        ulonglong2 cx2 = cxp[k], cy2 = cyp[k], cz2 = czp[k], cw2 = cwp[k];
        u64 sa = f2mul(qx2, cx2.x);
        u64 sb = f2mul(qx2, cx2.y);
        sa = f2fma(qy2, cy2.x, sa);  sb = f2fma(qy2, cy2.y, sb);
        sa = f2fma(qz2, cz2.x, sa);  sb = f2fma(qz2, cz2.y, sb);
        sa = f2fma(qw2, cw2.x, sa);  sb = f2fma(qw2, cw2.y, sb);
        float s0,s1,s2,s3; f2unpack(sa, s0, s1); f2unpack(sb, s2, s3);
        u64 ea = f2pack(ex2f(s0), ex2f(s1));
        u64 eb = f2pack(ex2f(s2), ex2f(s3));
        lA  = f2add(lA, ea);             lB  = f2add(lB, eb);
        axA = f2fma(ea, cx2.x, axA);     axB = f2fma(eb, cx2.y, axB);
        ayA = f2fma(ea, cy2.x, ayA);     ayB = f2fma(eb, cy2.y, ayB);
        azA = f2fma(ea, cz2.x, azA);     azB = f2fma(eb, cz2.y, azB);
        awA = f2fma(ea, cw2.x, awA);     awB = f2fma(eb, cw2.y, awB);
    }
    u64 l2  = f2add(lA, lB);
    u64 ax2 = f2add(axA, axB), ay2 = f2add(ayA, ayB);
    u64 az2 = f2add(azA, azB), aw2 = f2add(awA, awB);
    float l0,l1,x0,x1,y0,y1,z0,z1,w0,w1;
    f2unpack(l2, l0, l1);
    f2unpack(ax2, x0, x1); f2unpack(ay2, y0, y1);
    f2unpack(az2, z0, z1); f2unpack(aw2, w0, w1);
    float inv = 1.f / (l0 + l1);
    float4 r;
    r.x = (x0 + x1) * inv; r.y = (y0 + y1) * inv;
    r.z = (z0 + z1) * inv; r.w = (w0 + w1) * inv;
    *(float4*)(g_A + (size_t)tok*(NH*KL) + h*KL) = r;
}

// ============ Kernel 4: out = A @ M + (bo + sum_h Mb) (round-12 known-good) =
__global__ __launch_bounds__(256, 2) void final_kernel(
    float* __restrict__ out, const float* __restrict__ bo)
{
    __shared__ __align__(16) float Ast[16][258];   // [k][row]
    __shared__ __align__(16) float Bs[16][68];     // [k][j]
    const int tok0 = blockIdx.y * 256, j0 = blockIdx.x * 64;
    const int tid = threadIdx.x;
    const int tx = tid & 15, ty = tid >> 4;

    const int ar  = tid >> 2;          // base row 0..63 (+64*s)
    const int akq = (tid & 3) * 4;     // k quad 0,4,8,12
    const int bk  = tid >> 4;          // 0..15
    const int bjq = (tid & 15) * 4;

    u64 acc[8][4];
    #pragma unroll
    for (int i = 0; i < 8; ++i)
        #pragma unroll
        for (int j = 0; j < 4; ++j) acc[i][j] = 0ull;

    float4 aA[4], aB;
    #pragma unroll
    for (int s = 0; s < 4; ++s)
        aA[s] = *(const float4*)&g_A[(size_t)(tok0 + ar + 64*s)*(NH*KL) + akq];
    aB = *(const float4*)&g_M[(size_t)bk*DM + j0 + bjq];

    for (int k0 = 0; k0 < NH*KL; k0 += 16) {
        #pragma unroll
        for (int s = 0; s < 4; ++s) {
            int r = ar + 64*s;
            Ast[akq+0][r] = aA[s].x; Ast[akq+1][r] = aA[s].y;
            Ast[akq+2][r] = aA[s].z; Ast[akq+3][r] = aA[s].w;
        }
        *(float4*)&Bs[bk][bjq] = aB;
        __syncthreads();
        if (k0 + 16 < NH*KL) {
            #pragma unroll
            for (int s = 0; s < 4; ++s)
                aA[s] = *(const float4*)&g_A[(size_t)(tok0 + ar + 64*s)*(NH*KL) + k0 + 16 + akq];
            aB = *(const float4*)&g_M[(size_t)(k0 + 16 + bk)*DM + j0 + bjq];
        }
        #pragma unroll
        for (int k = 0; k < 16; ++k) {
            float4 bv = *(const float4*)&Bs[k][tx*4];
            u64 b0 = f2pack(bv.x, bv.x);
            u64 b1 = f2pack(bv.y, bv.y);
            u64 b2 = f2pack(bv.z, bv.z);
            u64 b3 = f2pack(bv.w, bv.w);
            #pragma unroll
            for (int i = 0; i < 8; ++i) {
                u64 a = *(const u64*)&Ast[k][ty*2 + 32*i];
                acc[i][0] = f2fma(a, b0, acc[i][0]);
                acc[i][1] = f2fma(a, b1, acc[i][1]);
                acc[i][2] = f2fma(a, b2, acc[i][2]);
                acc[i][3] = f2fma(a, b3, acc[i][3]);
            }
        }
        __syncthreads();
    }

    float4 bj = *(const float4*)&bo[j0 + tx*4];
    #pragma unroll
    for (int h = 0; h < NH; ++h) {
        float4 m = *(const float4*)&g_Mb[(size_t)h*DM + j0 + tx*4];
        bj.x += m.x; bj.y += m.y; bj.z += m.z; bj.w += m.w;
    }

    #pragma unroll
    for (int i = 0; i < 8; ++i) {
        float lo0, hi0, lo1, hi1, lo2, hi2, lo3, hi3;
        f2unpack(acc[i][0], lo0, hi0);
        f2unpack(acc[i][1], lo1, hi1);
        f2unpack(acc[i][2], lo2, hi2);
        f2unpack(acc[i][3], lo3, hi3);
        float4 ra, rb;
        ra.x = lo0 + bj.x; ra.y = lo1 + bj.y; ra.z = lo2 + bj.z; ra.w = lo3 + bj.w;
        rb.x = hi0 + bj.x; rb.y = hi1 + bj.y; rb.z = hi2 + bj.z; rb.w = hi3 + bj.w;
        size_t row = (size_t)(tok0 + ty*2 + 32*i);
        *(float4*)&out[row*DM + j0 + tx*4]       = ra;
        *(float4*)&out[(row + 1)*DM + j0 + tx*4] = rb;
    }
}

// ============================================================================
extern "C" void kernel_launch(void* const* d_in, const int* in_sizes, int n_in,
                              void* d_out, int out_size)
{
    const float* x    = (const float*)d_in[0];
    const float* Wq_d = (const float*)d_in[1];
    const float* bq_d = (const float*)d_in[2];
    const float* W_qk = (const float*)d_in[3];
    const float* b_qk = (const float*)d_in[4];
    const float* Wkv_d= (const float*)d_in[5];
    const float* bkv_d= (const float*)d_in[6];
    const float* Wv_u = (const float*)d_in[7];
    const float* bv_u = (const float*)d_in[8];
    const float* Wo   = (const float*)d_in[9];
    const float* bo   = (const float*)d_in[10];
    float* out = (float*)d_out;

    fused_pre_kernel<<<512, 128>>>(x, Wq_d, Wkv_d, Wv_u, Wo, bv_u);
    proj2_kernel<<<NT/16, 256>>>(bq_d, W_qk, b_qk, bkv_d);
    attn_kernel<<<dim3(SS/128, NH, BB), 128>>>();
    final_kernel<<<dim3(DM/64, NT/256), 256>>>(out, bo);
}